// round 7
// baseline (speedup 1.0000x reference)
#include <cuda_runtime.h>
#include <math.h>

#define N_   2
#define C_   256
#define H_   96
#define W_   96
#define G_   4
#define P_   9
#define GC_  64
#define HW_  (H_*W_)        // 9216
#define NPIX (N_*HW_)       // 18432
#define OM_  108            // G*P*3
#define MCNT ((float)(C_*H_*W_))

// ---------------- device scratch ----------------
__device__ float g_ctx [NPIX*C_];   // post-dwconv context, NHWC (raw; GN+GELU fused in k3)
__device__ float g_xt  [NPIX*C_];   // input x transposed to NHWC
__device__ float g_om  [NPIX*OM_];  // offset/mask head output
__device__ float g_omwT[C_*OM_];    // om_w transposed to [K=256][108]
__device__ float g_stats[4];        // sum0, sumsq0, sum1, sumsq1

__device__ __forceinline__ void ffma2(unsigned long long &acc,
                                      unsigned long long a,
                                      unsigned long long b) {
    asm("fma.rn.f32x2 %0, %1, %2, %0;" : "+l"(acc) : "l"(a), "l"(b));
}
__device__ __forceinline__ unsigned long long dup2(float v) {
    unsigned long long r;
    asm("mov.b64 %0, {%1, %1};" : "=l"(r) : "f"(v));
    return r;
}

// ---------------- k0: zero stats + transpose om_w ----------------
__global__ void k0_init(const float* __restrict__ om_w) {
    int idx = blockIdx.x * 256 + threadIdx.x;
    if (idx < 4) g_stats[idx] = 0.f;
    if (idx < C_*OM_) {
        int j = idx % OM_;
        int k = idx / OM_;
        g_omwT[idx] = om_w[j*C_ + k];
    }
}

// ---------------- k1: depthwise conv + bias, NHWC transposes, GN stats ----------------
__global__ void k1_dwconv(const float* __restrict__ x,
                          const float* __restrict__ dw_w,
                          const float* __restrict__ dw_b) {
    __shared__ float s_ctx[32][33];
    __shared__ float s_x  [32][33];
    __shared__ float2 red[256];

    int tx = threadIdx.x, ty = threadIdx.y;
    int w     = blockIdx.x * 32 + tx;
    int cbase = blockIdx.y * 32;
    int z = blockIdx.z;
    int n = z / H_, h = z - n * H_;

    float lsum = 0.f, lsq = 0.f;
    #pragma unroll
    for (int i = 0; i < 4; i++) {
        int cl = ty + i*8;
        int c  = cbase + cl;
        const float* xc = x + (long)((n*C_ + c)*H_) * W_;
        float acc = dw_b[c];
        #pragma unroll
        for (int dy = 0; dy < 3; dy++) {
            int hh = h + dy - 1;
            if (hh < 0 || hh >= H_) continue;
            #pragma unroll
            for (int dx = 0; dx < 3; dx++) {
                int ww = w + dx - 1;
                if (ww < 0 || ww >= W_) continue;
                acc += xc[hh*W_ + ww] * dw_w[c*9 + dy*3 + dx];
            }
        }
        s_ctx[cl][tx] = acc;
        s_x  [cl][tx] = xc[h*W_ + w];
        lsum += acc; lsq += acc*acc;
    }
    __syncthreads();
    #pragma unroll
    for (int i = 0; i < 4; i++) {
        int wl = ty + i*8;
        long addr = (long)((n*H_ + h)*W_ + blockIdx.x*32 + wl) * C_ + cbase + tx;
        g_ctx[addr] = s_ctx[tx][wl];
        g_xt [addr] = s_x  [tx][wl];
    }
    int t = ty*32 + tx;
    red[t] = make_float2(lsum, lsq);
    __syncthreads();
    for (int s = 128; s > 0; s >>= 1) {
        if (t < s) { red[t].x += red[t+s].x; red[t].y += red[t+s].y; }
        __syncthreads();
    }
    if (t == 0) {
        atomicAdd(&g_stats[2*n],   red[0].x);
        atomicAdd(&g_stats[2*n+1], red[0].y);
    }
}

// ---------------- k3: fused GN+GELU + GEMM  om = gelu(norm(ctx)) @ omw^T + b ----------------
// BM=64, BN=112(108 padded), BK=32, 128 threads, 8x8 thread tile via packed f32x2.
// B kept scalar in smem (half the crossbar bytes); duplicated in-register via mov.b64.
__global__ void __launch_bounds__(128) k3_gemm(const float* __restrict__ gn_w,
                                               const float* __restrict__ gn_b,
                                               const float* __restrict__ om_b) {
    __shared__ float As[32][68];      // [kk][pixel]
    __shared__ float Bs[32][116];     // scalar, interleaved: pos=(col&7)*14+(col>>3)

    int tid = threadIdx.x;
    int pb  = blockIdx.x * 64;
    int n   = pb / HW_;               // 9216 % 64 == 0: tile never crosses samples
    float mu = g_stats[2*n] / MCNT;
    float rs = rsqrtf(g_stats[2*n+1] / MCNT - mu*mu + 1e-5f);

    int tr  = tid >> 4;               // 0..7  -> pixels tr*8 .. tr*8+7
    int tc  = tid & 15;               // 0..15 -> cols tc*8 .. tc*8+7 (tc<14 real)
    bool active = tc < 14;
    int tcc = active ? tc : 0;

    unsigned long long acc[4][8];
    #pragma unroll
    for (int m = 0; m < 4; m++)
        #pragma unroll
        for (int j = 0; j < 8; j++) acc[m][j] = 0ull;

    for (int k0 = 0; k0 < C_; k0 += 32) {
        // A tile: 64x32, GN + exact GELU fused on load
        #pragma unroll
        for (int it = 0; it < 16; it++) {
            int e  = tid + it*128;
            int i  = e >> 5;
            int kk = e & 31;
            int c  = k0 + kk;
            float v = g_ctx[(long)(pb + i)*C_ + c];
            v = (v - mu) * rs * gn_w[c] + gn_b[c];
            v = 0.5f * v * (1.f + erff(v * 0.70710678118654752f));
            As[kk][i] = v;
        }
        // B tile: 112x32 scalar, position (col&7)*14 + (col>>3)
        #pragma unroll
        for (int it = 0; it < 28; it++) {
            int e  = tid + it*128;
            int kk = e / 112;
            int j  = e - kk*112;
            float v = (j < OM_) ? g_omwT[(k0 + kk)*OM_ + j] : 0.f;
            Bs[kk][(j & 7)*14 + (j >> 3)] = v;
        }
        __syncthreads();
        #pragma unroll
        for (int kk = 0; kk < 32; kk++) {
            unsigned long long a[4], b[8];
            #pragma unroll
            for (int m = 0; m < 4; m++)
                a[m] = *reinterpret_cast<const unsigned long long*>(&As[kk][tr*8 + 2*m]);
            #pragma unroll
            for (int j = 0; j < 8; j++)
                b[j] = dup2(Bs[kk][j*14 + tcc]);
            #pragma unroll
            for (int m = 0; m < 4; m++)
                #pragma unroll
                for (int j = 0; j < 8; j++) ffma2(acc[m][j], a[m], b[j]);
        }
        __syncthreads();
    }

    if (active) {
        #pragma unroll
        for (int j = 0; j < 8; j++) {
            int col = tc*8 + j;
            if (col < OM_) {
                float bb = om_b[col];
                #pragma unroll
                for (int m = 0; m < 4; m++) {
                    unsigned long long v = acc[m][j];
                    float lo = __uint_as_float((unsigned)(v & 0xffffffffu));
                    float hi = __uint_as_float((unsigned)(v >> 32));
                    int row0 = pb + tr*8 + 2*m;
                    g_om[(long)row0*OM_ + col]     = lo + bb;
                    g_om[(long)(row0+1)*OM_ + col] = hi + bb;
                }
            }
        }
    }
}

// ---------------- k4: softmax*uncertainty + DCNv3 sampling, float4 channels ----------------
// One block = 16 consecutive-w pixels, 256 threads.
// thread: 4 channels (c4 = (t&63)*4), 4 consecutive pixels (quarter = t>>6).
__global__ void __launch_bounds__(256, 4) k4_sample(const float* __restrict__ unc,
                                                    float* __restrict__ out) {
    __shared__ float  om_s[16][112];
    __shared__ float  mmax[64], mscale[64];
    __shared__ int4   toff[576];
    __shared__ float4 twt [576];

    int bid = blockIdx.x;
    int w0 = (bid % 6) * 16;
    int h  = (bid / 6) % H_;
    int n  = bid / (6 * H_);
    int pixbase = (n*H_ + h)*W_ + w0;
    int tid = threadIdx.x;

    for (int idx = tid; idx < 16*OM_; idx += 256) {
        int pix = idx / OM_, j = idx - pix*OM_;
        om_s[pix][j] = g_om[(long)(pixbase + pix)*OM_ + j];
    }
    __syncthreads();

    // softmax stats per (pix, g): 64 pairs
    if (tid < 64) {
        int pix = tid >> 2, g = tid & 3;
        const float* r = &om_s[pix][72 + g*9];
        float m = r[0];
        #pragma unroll
        for (int p = 1; p < 9; p++) m = fmaxf(m, r[p]);
        float s = 0.f;
        #pragma unroll
        for (int p = 0; p < 9; p++) s += expf(r[p] - m);
        float u = unc[pixbase + pix];
        mmax[tid]   = m;
        mscale[tid] = u / s;
    }
    __syncthreads();

    // tap params per (pix, g, p): 576 entries; vector smem writes
    for (int idx = tid; idx < 576; idx += 256) {
        int pix = idx / 36, gp = idx - pix*36;
        int g = gp / 9, p = gp - g*9;
        float offx = om_s[pix][gp*2];
        float offy = om_s[pix][gp*2 + 1];
        float mval = expf(om_s[pix][72 + gp] - mmax[pix*4 + g]) * mscale[pix*4 + g];
        float tx = (float)(w0 + pix + (p/3) - 1) + offx;   // x-major point ordering
        float ty = (float)(h + (p - (p/3)*3) - 1) + offy;
        float fx = floorf(tx), fy = floorf(ty);
        int x0i = (int)fx, y0i = (int)fy;
        float wx = tx - fx, wy = ty - fy;
        int4 o; float4 wv;
        {
            int cy0 = min(max(y0i, 0), H_-1),   cy1 = min(max(y0i+1, 0), H_-1);
            int cx0 = min(max(x0i, 0), W_-1),   cx1 = min(max(x0i+1, 0), W_-1);
            bool vy0 = (y0i >= 0) && (y0i < H_);
            bool vy1 = (y0i+1 >= 0) && (y0i+1 < H_);
            bool vx0 = (x0i >= 0) && (x0i < W_);
            bool vx1 = (x0i+1 >= 0) && (x0i+1 < W_);
            o.x = ((n*H_ + cy0)*W_ + cx0) * C_;
            o.y = ((n*H_ + cy0)*W_ + cx1) * C_;
            o.z = ((n*H_ + cy1)*W_ + cx0) * C_;
            o.w = ((n*H_ + cy1)*W_ + cx1) * C_;
            wv.x = (vy0 && vx0) ? mval * (1.f-wy)*(1.f-wx) : 0.f;
            wv.y = (vy0 && vx1) ? mval * (1.f-wy)*wx       : 0.f;
            wv.z = (vy1 && vx0) ? mval * wy*(1.f-wx)       : 0.f;
            wv.w = (vy1 && vx1) ? mval * wy*wx             : 0.f;
        }
        toff[idx] = o;
        twt [idx] = wv;
    }
    __syncthreads();

    int c4      = (tid & 63) * 4;
    int quarter = tid >> 6;               // 0..3 -> pixels quarter*4 .. +3
    int gbase   = (c4 >> 6) * 9;
    const float* xt_c = g_xt + c4;
    float4 res[4];

    #pragma unroll
    for (int k = 0; k < 4; k++) {
        int pix = quarter*4 + k;
        float4 acc = make_float4(0.f, 0.f, 0.f, 0.f);
        int e0 = pix*36 + gbase;
        #pragma unroll
        for (int p = 0; p < 9; p++) {
            int e = e0 + p;
            int4   o  = toff[e];
            float4 wv = twt[e];
            const float4 v0 = *reinterpret_cast<const float4*>(xt_c + o.x);
            const float4 v1 = *reinterpret_cast<const float4*>(xt_c + o.y);
            const float4 v2 = *reinterpret_cast<const float4*>(xt_c + o.z);
            const float4 v3 = *reinterpret_cast<const float4*>(xt_c + o.w);
            acc.x += wv.x*v0.x + wv.y*v1.x + wv.z*v2.x + wv.w*v3.x;
            acc.y += wv.x*v0.y + wv.y*v1.y + wv.z*v2.y + wv.w*v3.y;
            acc.z += wv.x*v0.z + wv.y*v1.z + wv.z*v2.z + wv.w*v3.z;
            acc.w += wv.x*v0.w + wv.y*v1.w + wv.z*v2.w + wv.w*v3.w;
        }
        res[k] = acc;
    }

    // NCHW output: per channel, 4 consecutive w -> one float4 store
    #pragma unroll
    for (int u = 0; u < 4; u++) {
        int c = c4 + u;
        long base = ((long)(n*C_ + c)*H_ + h)*W_ + w0 + quarter*4;
        *reinterpret_cast<float4*>(out + base) =
            make_float4((&res[0].x)[u], (&res[1].x)[u], (&res[2].x)[u], (&res[3].x)[u]);
    }
}

// ---------------- launch ----------------
extern "C" void kernel_launch(void* const* d_in, const int* in_sizes, int n_in,
                              void* d_out, int out_size) {
    const float* x    = (const float*)d_in[0];
    const float* unc  = (const float*)d_in[1];
    const float* dw_w = (const float*)d_in[2];
    const float* dw_b = (const float*)d_in[3];
    const float* gn_w = (const float*)d_in[4];
    const float* gn_b = (const float*)d_in[5];
    const float* om_w = (const float*)d_in[6];
    const float* om_b = (const float*)d_in[7];
    float* out = (float*)d_out;

    k0_init   <<<112, 256>>>(om_w);
    k1_dwconv <<<dim3(3, 8, N_*H_), dim3(32, 8)>>>(x, dw_w, dw_b);
    k3_gemm   <<<NPIX/64, 128>>>(gn_w, gn_b, om_b);
    k4_sample <<<NPIX/16, 256>>>(unc, out);
}

// round 8
// speedup vs baseline: 1.2911x; 1.2911x over previous
#include <cuda_runtime.h>
#include <math.h>

#define N_   2
#define C_   256
#define H_   96
#define W_   96
#define G_   4
#define P_   9
#define GC_  64
#define HW_  (H_*W_)        // 9216
#define NPIX (N_*HW_)       // 18432
#define OM_  108            // G*P*3
#define MCNT ((float)(C_*H_*W_))

// ---------------- device scratch ----------------
__device__ float g_ctx [NPIX*C_];   // post-dwconv context, NHWC (raw; GN+GELU fused in k3)
__device__ float g_xt  [NPIX*C_];   // input x transposed to NHWC
__device__ float g_om  [NPIX*OM_];  // offset/mask head output, K-half 0 (+bias)
__device__ float g_om2 [NPIX*OM_];  // offset/mask head output, K-half 1
__device__ float g_omwT[C_*OM_];    // om_w transposed to [K=256][108]
__device__ float g_stats[4];        // sum0, sumsq0, sum1, sumsq1

__device__ __forceinline__ void ffma2(unsigned long long &acc,
                                      unsigned long long a,
                                      unsigned long long b) {
    asm("fma.rn.f32x2 %0, %1, %2, %0;" : "+l"(acc) : "l"(a), "l"(b));
}

// ---------------- k0: zero stats + transpose om_w ----------------
__global__ void k0_init(const float* __restrict__ om_w) {
    int idx = blockIdx.x * 256 + threadIdx.x;
    if (idx < 4) g_stats[idx] = 0.f;
    if (idx < C_*OM_) {
        int j = idx % OM_;
        int k = idx / OM_;
        g_omwT[idx] = om_w[j*C_ + k];
    }
}

// ---------------- k1: depthwise conv + bias, NHWC transposes, GN stats ----------------
__global__ void k1_dwconv(const float* __restrict__ x,
                          const float* __restrict__ dw_w,
                          const float* __restrict__ dw_b) {
    __shared__ float s_ctx[32][33];
    __shared__ float s_x  [32][33];
    __shared__ float2 red[256];

    int tx = threadIdx.x, ty = threadIdx.y;
    int w     = blockIdx.x * 32 + tx;
    int cbase = blockIdx.y * 32;
    int z = blockIdx.z;
    int n = z / H_, h = z - n * H_;

    float lsum = 0.f, lsq = 0.f;
    #pragma unroll
    for (int i = 0; i < 4; i++) {
        int cl = ty + i*8;
        int c  = cbase + cl;
        const float* xc = x + (long)((n*C_ + c)*H_) * W_;
        float acc = dw_b[c];
        #pragma unroll
        for (int dy = 0; dy < 3; dy++) {
            int hh = h + dy - 1;
            if (hh < 0 || hh >= H_) continue;
            #pragma unroll
            for (int dx = 0; dx < 3; dx++) {
                int ww = w + dx - 1;
                if (ww < 0 || ww >= W_) continue;
                acc += xc[hh*W_ + ww] * dw_w[c*9 + dy*3 + dx];
            }
        }
        s_ctx[cl][tx] = acc;
        s_x  [cl][tx] = xc[h*W_ + w];
        lsum += acc; lsq += acc*acc;
    }
    __syncthreads();
    #pragma unroll
    for (int i = 0; i < 4; i++) {
        int wl = ty + i*8;
        long addr = (long)((n*H_ + h)*W_ + blockIdx.x*32 + wl) * C_ + cbase + tx;
        g_ctx[addr] = s_ctx[tx][wl];
        g_xt [addr] = s_x  [tx][wl];
    }
    int t = ty*32 + tx;
    red[t] = make_float2(lsum, lsq);
    __syncthreads();
    for (int s = 128; s > 0; s >>= 1) {
        if (t < s) { red[t].x += red[t+s].x; red[t].y += red[t+s].y; }
        __syncthreads();
    }
    if (t == 0) {
        atomicAdd(&g_stats[2*n],   red[0].x);
        atomicAdd(&g_stats[2*n+1], red[0].y);
    }
}

// ---------------- k3: fused GN+GELU + GEMM, K-split by 2 for occupancy ----------------
// BM=64, BN=112(108 padded), BK=32, 128 threads, 8x8 thread tile via packed f32x2.
// blockIdx.y selects K half; each half writes its own partial buffer (k4 sums them).
__global__ void __launch_bounds__(128) k3_gemm(const float* __restrict__ gn_w,
                                               const float* __restrict__ gn_b,
                                               const float* __restrict__ om_b) {
    __shared__ float  As[32][68];     // [kk][pixel]
    __shared__ float2 Bs[32][114];    // duplicated (v,v), j-major interleaved layout

    int tid = threadIdx.x;
    int pb  = blockIdx.x * 64;
    int kbase = blockIdx.y * 128;
    int n   = pb / HW_;               // 9216 % 64 == 0: tile never crosses samples
    float mu = g_stats[2*n] / MCNT;
    float rs = rsqrtf(g_stats[2*n+1] / MCNT - mu*mu + 1e-5f);

    int tr  = tid >> 4;               // 0..7  -> pixels tr*8 .. tr*8+7
    int tc  = tid & 15;               // 0..15 -> cols tc*8 .. tc*8+7 (tc<14 real)
    bool active = tc < 14;
    int tcc = active ? tc : 0;

    unsigned long long acc[4][8];
    #pragma unroll
    for (int m = 0; m < 4; m++)
        #pragma unroll
        for (int j = 0; j < 8; j++) acc[m][j] = 0ull;

    for (int k0 = kbase; k0 < kbase + 128; k0 += 32) {
        // A tile: 64x32, GN + exact GELU fused on load (each ctx element hit once globally)
        #pragma unroll
        for (int it = 0; it < 16; it++) {
            int e  = tid + it*128;
            int i  = e >> 5;
            int kk = e & 31;
            int c  = k0 + kk;
            float v = g_ctx[(long)(pb + i)*C_ + c];
            v = (v - mu) * rs * gn_w[c] + gn_b[c];
            v = 0.5f * v * (1.f + erff(v * 0.70710678118654752f));
            As[kk][i] = v;
        }
        // B tile: 112x32, duplicated pairs, position (col&7)*14 + (col>>3)
        #pragma unroll
        for (int it = 0; it < 28; it++) {
            int e  = tid + it*128;
            int kk = e / 112;
            int j  = e - kk*112;
            float v = (j < OM_) ? g_omwT[(k0 + kk)*OM_ + j] : 0.f;
            Bs[kk][(j & 7)*14 + (j >> 3)] = make_float2(v, v);
        }
        __syncthreads();
        #pragma unroll
        for (int kk = 0; kk < 32; kk++) {
            unsigned long long a[4], b[8];
            #pragma unroll
            for (int m = 0; m < 4; m++)
                a[m] = *reinterpret_cast<const unsigned long long*>(&As[kk][tr*8 + 2*m]);
            #pragma unroll
            for (int j = 0; j < 8; j++)
                b[j] = *reinterpret_cast<const unsigned long long*>(&Bs[kk][j*14 + tcc]);
            #pragma unroll
            for (int m = 0; m < 4; m++)
                #pragma unroll
                for (int j = 0; j < 8; j++) ffma2(acc[m][j], a[m], b[j]);
        }
        __syncthreads();
    }

    if (active) {
        float* dst = (blockIdx.y == 0) ? g_om : g_om2;
        #pragma unroll
        for (int j = 0; j < 8; j++) {
            int col = tc*8 + j;
            if (col < OM_) {
                float bb = (blockIdx.y == 0) ? om_b[col] : 0.f;
                #pragma unroll
                for (int m = 0; m < 4; m++) {
                    unsigned long long v = acc[m][j];
                    float lo = __uint_as_float((unsigned)(v & 0xffffffffu));
                    float hi = __uint_as_float((unsigned)(v >> 32));
                    int row0 = pb + tr*8 + 2*m;
                    dst[(long)row0*OM_ + col]     = lo + bb;
                    dst[(long)(row0+1)*OM_ + col] = hi + bb;
                }
            }
        }
    }
}

// ---------------- k4: softmax*uncertainty + DCNv3 sampling, float4 channels ----------------
// One block = 32 consecutive-w pixels, 256 threads.
// thread: 4 channels (c4 = (t&63)*4), 8 consecutive pixels (quarter = t>>6).
__global__ void k4_sample(const float* __restrict__ unc, float* __restrict__ out) {
    __shared__ float  om_s[32][112];
    __shared__ float  mmax[128], mscale[128];
    __shared__ int4   toff[1152];
    __shared__ float4 twt [1152];

    int bid = blockIdx.x;
    int w0 = (bid % 3) * 32;
    int h  = (bid / 3) % H_;
    int n  = bid / (3 * H_);
    int pixbase = (n*H_ + h)*W_ + w0;
    int tid = threadIdx.x;

    for (int idx = tid; idx < 32*OM_; idx += 256) {
        int pix = idx / OM_, j = idx - pix*OM_;
        long a = (long)(pixbase + pix)*OM_ + j;
        om_s[pix][j] = g_om[a] + g_om2[a];     // sum K-split partials
    }
    __syncthreads();

    // softmax stats per (pix, g): 128 pairs
    if (tid < 128) {
        int pix = tid >> 2, g = tid & 3;
        const float* r = &om_s[pix][72 + g*9];
        float m = r[0];
        #pragma unroll
        for (int p = 1; p < 9; p++) m = fmaxf(m, r[p]);
        float s = 0.f;
        #pragma unroll
        for (int p = 0; p < 9; p++) s += expf(r[p] - m);
        float u = unc[pixbase + pix];
        mmax[tid]   = m;
        mscale[tid] = u / s;
    }
    __syncthreads();

    // tap params per (pix, g, p): 1152 entries; vector smem writes
    for (int idx = tid; idx < 1152; idx += 256) {
        int pix = idx / 36, gp = idx - pix*36;
        int g = gp / 9, p = gp - g*9;
        float offx = om_s[pix][gp*2];
        float offy = om_s[pix][gp*2 + 1];
        float mval = expf(om_s[pix][72 + gp] - mmax[pix*4 + g]) * mscale[pix*4 + g];
        float tx = (float)(w0 + pix + (p/3) - 1) + offx;   // x-major point ordering
        float ty = (float)(h + (p - (p/3)*3) - 1) + offy;
        float fx = floorf(tx), fy = floorf(ty);
        int x0i = (int)fx, y0i = (int)fy;
        float wx = tx - fx, wy = ty - fy;
        int4 o; float4 wv;
        {
            int cy0 = min(max(y0i, 0), H_-1),   cy1 = min(max(y0i+1, 0), H_-1);
            int cx0 = min(max(x0i, 0), W_-1),   cx1 = min(max(x0i+1, 0), W_-1);
            bool vy0 = (y0i >= 0) && (y0i < H_);
            bool vy1 = (y0i+1 >= 0) && (y0i+1 < H_);
            bool vx0 = (x0i >= 0) && (x0i < W_);
            bool vx1 = (x0i+1 >= 0) && (x0i+1 < W_);
            o.x = ((n*H_ + cy0)*W_ + cx0) * C_;
            o.y = ((n*H_ + cy0)*W_ + cx1) * C_;
            o.z = ((n*H_ + cy1)*W_ + cx0) * C_;
            o.w = ((n*H_ + cy1)*W_ + cx1) * C_;
            wv.x = (vy0 && vx0) ? mval * (1.f-wy)*(1.f-wx) : 0.f;
            wv.y = (vy0 && vx1) ? mval * (1.f-wy)*wx       : 0.f;
            wv.z = (vy1 && vx0) ? mval * wy*(1.f-wx)       : 0.f;
            wv.w = (vy1 && vx1) ? mval * wy*wx             : 0.f;
        }
        toff[idx] = o;
        twt [idx] = wv;
    }
    __syncthreads();

    int c4      = (tid & 63) * 4;
    int quarter = tid >> 6;               // 0..3 -> pixels quarter*8 .. +7
    int gbase   = (c4 >> 6) * 9;
    const float* xt_c = g_xt + c4;
    float4 res[8];

    #pragma unroll
    for (int k = 0; k < 8; k++) {
        int pix = quarter*8 + k;
        float4 acc = make_float4(0.f, 0.f, 0.f, 0.f);
        int e0 = pix*36 + gbase;
        #pragma unroll
        for (int p = 0; p < 9; p++) {
            int e = e0 + p;
            int4   o  = toff[e];
            float4 wv = twt[e];
            const float4 v0 = *reinterpret_cast<const float4*>(xt_c + o.x);
            const float4 v1 = *reinterpret_cast<const float4*>(xt_c + o.y);
            const float4 v2 = *reinterpret_cast<const float4*>(xt_c + o.z);
            const float4 v3 = *reinterpret_cast<const float4*>(xt_c + o.w);
            // per-tap tree then one add into acc: critical chain 9, not 36
            float tx0 = wv.x*v0.x + wv.y*v1.x + wv.z*v2.x + wv.w*v3.x;
            float ty0 = wv.x*v0.y + wv.y*v1.y + wv.z*v2.y + wv.w*v3.y;
            float tz0 = wv.x*v0.z + wv.y*v1.z + wv.z*v2.z + wv.w*v3.z;
            float tw0 = wv.x*v0.w + wv.y*v1.w + wv.z*v2.w + wv.w*v3.w;
            acc.x += tx0; acc.y += ty0; acc.z += tz0; acc.w += tw0;
        }
        res[k] = acc;
    }

    // NCHW output: per channel, 8 consecutive w -> two float4 stores
    #pragma unroll
    for (int u = 0; u < 4; u++) {
        int c = c4 + u;
        long base = ((long)(n*C_ + c)*H_ + h)*W_ + w0 + quarter*8;
        float e0 = (&res[0].x)[u], e1 = (&res[1].x)[u], e2 = (&res[2].x)[u], e3 = (&res[3].x)[u];
        float e4 = (&res[4].x)[u], e5 = (&res[5].x)[u], e6 = (&res[6].x)[u], e7 = (&res[7].x)[u];
        *reinterpret_cast<float4*>(out + base)     = make_float4(e0, e1, e2, e3);
        *reinterpret_cast<float4*>(out + base + 4) = make_float4(e4, e5, e6, e7);
    }
}

// ---------------- launch ----------------
extern "C" void kernel_launch(void* const* d_in, const int* in_sizes, int n_in,
                              void* d_out, int out_size) {
    const float* x    = (const float*)d_in[0];
    const float* unc  = (const float*)d_in[1];
    const float* dw_w = (const float*)d_in[2];
    const float* dw_b = (const float*)d_in[3];
    const float* gn_w = (const float*)d_in[4];
    const float* gn_b = (const float*)d_in[5];
    const float* om_w = (const float*)d_in[6];
    const float* om_b = (const float*)d_in[7];
    float* out = (float*)d_out;

    k0_init   <<<112, 256>>>(om_w);
    k1_dwconv <<<dim3(3, 8, N_*H_), dim3(32, 8)>>>(x, dw_w, dw_b);
    k3_gemm   <<<dim3(NPIX/64, 2), 128>>>(gn_w, gn_b, om_b);
    k4_sample <<<NPIX/32, 256>>>(unc, out);
}

// round 9
// speedup vs baseline: 1.7259x; 1.3368x over previous
#include <cuda_runtime.h>
#include <cuda_fp16.h>
#include <math.h>

#define N_   2
#define C_   256
#define H_   96
#define W_   96
#define G_   4
#define P_   9
#define GC_  64
#define HW_  (H_*W_)        // 9216
#define NPIX (N_*HW_)       // 18432
#define OM_  108            // G*P*3
#define MCNT ((float)(C_*H_*W_))

// ---------------- device scratch ----------------
__device__ float  g_ctx [NPIX*C_];   // post-dwconv context, NHWC (raw; GN+GELU fused in k3)
__device__ __half g_xh  [NPIX*C_];   // input x transposed to NHWC, fp16 (sampling source)
__device__ float  g_om  [NPIX*OM_];  // offset/mask head output
__device__ float  g_omwT[C_*OM_];    // om_w transposed to [K=256][108]
__device__ float  g_stats[4];        // sum0, sumsq0, sum1, sumsq1

__device__ __forceinline__ void ffma2(unsigned long long &acc,
                                      unsigned long long a,
                                      unsigned long long b) {
    asm("fma.rn.f32x2 %0, %1, %2, %0;" : "+l"(acc) : "l"(a), "l"(b));
}

// ---------------- k0: zero stats + transpose om_w ----------------
__global__ void k0_init(const float* __restrict__ om_w) {
    int idx = blockIdx.x * 256 + threadIdx.x;
    if (idx < 4) g_stats[idx] = 0.f;
    if (idx < C_*OM_) {
        int j = idx % OM_;
        int k = idx / OM_;
        g_omwT[idx] = om_w[j*C_ + k];
    }
}

// ---------------- k1: depthwise conv + bias, NHWC transposes, GN stats ----------------
__global__ void k1_dwconv(const float* __restrict__ x,
                          const float* __restrict__ dw_w,
                          const float* __restrict__ dw_b) {
    __shared__ float s_ctx[32][33];
    __shared__ float s_x  [32][33];
    __shared__ float2 red[256];

    int tx = threadIdx.x, ty = threadIdx.y;
    int w     = blockIdx.x * 32 + tx;
    int cbase = blockIdx.y * 32;
    int z = blockIdx.z;
    int n = z / H_, h = z - n * H_;

    float lsum = 0.f, lsq = 0.f;
    #pragma unroll
    for (int i = 0; i < 4; i++) {
        int cl = ty + i*8;
        int c  = cbase + cl;
        const float* xc = x + (long)((n*C_ + c)*H_) * W_;
        float acc = dw_b[c];
        #pragma unroll
        for (int dy = 0; dy < 3; dy++) {
            int hh = h + dy - 1;
            if (hh < 0 || hh >= H_) continue;
            #pragma unroll
            for (int dx = 0; dx < 3; dx++) {
                int ww = w + dx - 1;
                if (ww < 0 || ww >= W_) continue;
                acc += xc[hh*W_ + ww] * dw_w[c*9 + dy*3 + dx];
            }
        }
        s_ctx[cl][tx] = acc;
        s_x  [cl][tx] = xc[h*W_ + w];
        lsum += acc; lsq += acc*acc;
    }
    __syncthreads();
    #pragma unroll
    for (int i = 0; i < 4; i++) {
        int wl = ty + i*8;
        long addr = (long)((n*H_ + h)*W_ + blockIdx.x*32 + wl) * C_ + cbase + tx;
        g_ctx[addr] = s_ctx[tx][wl];
        g_xh [addr] = __float2half(s_x[tx][wl]);
    }
    int t = ty*32 + tx;
    red[t] = make_float2(lsum, lsq);
    __syncthreads();
    for (int s = 128; s > 0; s >>= 1) {
        if (t < s) { red[t].x += red[t+s].x; red[t].y += red[t+s].y; }
        __syncthreads();
    }
    if (t == 0) {
        atomicAdd(&g_stats[2*n],   red[0].x);
        atomicAdd(&g_stats[2*n+1], red[0].y);
    }
}

// ---------------- k3: fused GN+GELU + GEMM  om = gelu(norm(ctx)) @ omw^T + b ----------------
// BM=64, BN=112(108 padded), BK=32, 128 threads, 8x8 thread tile via packed f32x2.
// (R5 configuration — best measured.)
__global__ void __launch_bounds__(128) k3_gemm(const float* __restrict__ gn_w,
                                               const float* __restrict__ gn_b,
                                               const float* __restrict__ om_b) {
    __shared__ float  As[32][68];     // [kk][pixel]
    __shared__ float2 Bs[32][114];    // duplicated (v,v), j-major interleaved layout

    int tid = threadIdx.x;
    int pb  = blockIdx.x * 64;
    int n   = pb / HW_;               // 9216 % 64 == 0: tile never crosses samples
    float mu = g_stats[2*n] / MCNT;
    float rs = rsqrtf(g_stats[2*n+1] / MCNT - mu*mu + 1e-5f);

    int tr  = tid >> 4;               // 0..7  -> pixels tr*8 .. tr*8+7
    int tc  = tid & 15;               // 0..15 -> cols tc*8 .. tc*8+7 (tc<14 real)
    bool active = tc < 14;
    int tcc = active ? tc : 0;

    unsigned long long acc[4][8];
    #pragma unroll
    for (int m = 0; m < 4; m++)
        #pragma unroll
        for (int j = 0; j < 8; j++) acc[m][j] = 0ull;

    for (int k0 = 0; k0 < C_; k0 += 32) {
        // A tile: 64x32, GN + exact GELU fused on load
        #pragma unroll
        for (int it = 0; it < 16; it++) {
            int e  = tid + it*128;
            int i  = e >> 5;
            int kk = e & 31;
            int c  = k0 + kk;
            float v = g_ctx[(long)(pb + i)*C_ + c];
            v = (v - mu) * rs * gn_w[c] + gn_b[c];
            v = 0.5f * v * (1.f + erff(v * 0.70710678118654752f));
            As[kk][i] = v;
        }
        // B tile: 112x32, duplicated pairs, position (col&7)*14 + (col>>3)
        #pragma unroll
        for (int it = 0; it < 28; it++) {
            int e  = tid + it*128;
            int kk = e / 112;
            int j  = e - kk*112;
            float v = (j < OM_) ? g_omwT[(k0 + kk)*OM_ + j] : 0.f;
            Bs[kk][(j & 7)*14 + (j >> 3)] = make_float2(v, v);
        }
        __syncthreads();
        #pragma unroll
        for (int kk = 0; kk < 32; kk++) {
            unsigned long long a[4], b[8];
            #pragma unroll
            for (int m = 0; m < 4; m++)
                a[m] = *reinterpret_cast<const unsigned long long*>(&As[kk][tr*8 + 2*m]);
            #pragma unroll
            for (int j = 0; j < 8; j++)
                b[j] = *reinterpret_cast<const unsigned long long*>(&Bs[kk][j*14 + tcc]);
            #pragma unroll
            for (int m = 0; m < 4; m++)
                #pragma unroll
                for (int j = 0; j < 8; j++) ffma2(acc[m][j], a[m], b[j]);
        }
        __syncthreads();
    }

    if (active) {
        #pragma unroll
        for (int j = 0; j < 8; j++) {
            int col = tc*8 + j;
            if (col < OM_) {
                float bb = om_b[col];
                #pragma unroll
                for (int m = 0; m < 4; m++) {
                    unsigned long long v = acc[m][j];
                    float lo = __uint_as_float((unsigned)(v & 0xffffffffu));
                    float hi = __uint_as_float((unsigned)(v >> 32));
                    int row0 = pb + tr*8 + 2*m;
                    g_om[(long)row0*OM_ + col]     = lo + bb;
                    g_om[(long)(row0+1)*OM_ + col] = hi + bb;
                }
            }
        }
    }
}

// ---------------- k4: softmax*uncertainty + DCNv3 sampling, fp16 gathers ----------------
// One block = 32 consecutive-w pixels, 256 threads.
// thread: 8 channels (c8 = (t&31)*8 as half8 = one LDG.128), 4 pixels (pslot = t>>5).
__device__ __forceinline__ void corner_acc(const __half* p, float w, float* r) {
    uint4 raw = *reinterpret_cast<const uint4*>(p);
    float2 f0 = __half22float2(*reinterpret_cast<__half2*>(&raw.x));
    float2 f1 = __half22float2(*reinterpret_cast<__half2*>(&raw.y));
    float2 f2 = __half22float2(*reinterpret_cast<__half2*>(&raw.z));
    float2 f3 = __half22float2(*reinterpret_cast<__half2*>(&raw.w));
    r[0] += w*f0.x; r[1] += w*f0.y; r[2] += w*f1.x; r[3] += w*f1.y;
    r[4] += w*f2.x; r[5] += w*f2.y; r[6] += w*f3.x; r[7] += w*f3.y;
}

__global__ void k4_sample(const float* __restrict__ unc, float* __restrict__ out) {
    __shared__ float  om_s[32][112];
    __shared__ float  mmax[128], mscale[128];
    __shared__ int4   toff[1152];
    __shared__ float4 twt [1152];

    int bid = blockIdx.x;
    int w0 = (bid % 3) * 32;
    int h  = (bid / 3) % H_;
    int n  = bid / (3 * H_);
    int pixbase = (n*H_ + h)*W_ + w0;
    int tid = threadIdx.x;

    for (int idx = tid; idx < 32*OM_; idx += 256) {
        int pix = idx / OM_, j = idx - pix*OM_;
        om_s[pix][j] = g_om[(long)(pixbase + pix)*OM_ + j];
    }
    __syncthreads();

    // softmax stats per (pix, g): 128 pairs
    if (tid < 128) {
        int pix = tid >> 2, g = tid & 3;
        const float* r = &om_s[pix][72 + g*9];
        float m = r[0];
        #pragma unroll
        for (int p = 1; p < 9; p++) m = fmaxf(m, r[p]);
        float s = 0.f;
        #pragma unroll
        for (int p = 0; p < 9; p++) s += expf(r[p] - m);
        float u = unc[pixbase + pix];
        mmax[tid]   = m;
        mscale[tid] = u / s;
    }
    __syncthreads();

    // tap params per (pix, g, p): 1152 entries
    for (int idx = tid; idx < 1152; idx += 256) {
        int pix = idx / 36, gp = idx - pix*36;
        int g = gp / 9, p = gp - g*9;
        float offx = om_s[pix][gp*2];
        float offy = om_s[pix][gp*2 + 1];
        float mval = expf(om_s[pix][72 + gp] - mmax[pix*4 + g]) * mscale[pix*4 + g];
        float tx = (float)(w0 + pix + (p/3) - 1) + offx;   // x-major point ordering
        float ty = (float)(h + (p - (p/3)*3) - 1) + offy;
        float fx = floorf(tx), fy = floorf(ty);
        int x0i = (int)fx, y0i = (int)fy;
        float wx = tx - fx, wy = ty - fy;
        int4 o; float4 wv;
        {
            int cy0 = min(max(y0i, 0), H_-1),   cy1 = min(max(y0i+1, 0), H_-1);
            int cx0 = min(max(x0i, 0), W_-1),   cx1 = min(max(x0i+1, 0), W_-1);
            bool vy0 = (y0i >= 0) && (y0i < H_);
            bool vy1 = (y0i+1 >= 0) && (y0i+1 < H_);
            bool vx0 = (x0i >= 0) && (x0i < W_);
            bool vx1 = (x0i+1 >= 0) && (x0i+1 < W_);
            o.x = ((n*H_ + cy0)*W_ + cx0) * C_;
            o.y = ((n*H_ + cy0)*W_ + cx1) * C_;
            o.z = ((n*H_ + cy1)*W_ + cx0) * C_;
            o.w = ((n*H_ + cy1)*W_ + cx1) * C_;
            wv.x = (vy0 && vx0) ? mval * (1.f-wy)*(1.f-wx) : 0.f;
            wv.y = (vy0 && vx1) ? mval * (1.f-wy)*wx       : 0.f;
            wv.z = (vy1 && vx0) ? mval * wy*(1.f-wx)       : 0.f;
            wv.w = (vy1 && vx1) ? mval * wy*wx             : 0.f;
        }
        toff[idx] = o;
        twt [idx] = wv;
    }
    __syncthreads();

    int c8    = (tid & 31) * 8;            // 8 channels -> one half8 LDG.128 per corner
    int pslot = tid >> 5;                  // 0..7 -> pixels pslot*4 .. +3
    int gbase = (c8 >> 6) * 9;
    const __half* xh = g_xh + c8;
    float res[4][8];
    #pragma unroll
    for (int k = 0; k < 4; k++)
        #pragma unroll
        for (int u = 0; u < 8; u++) res[k][u] = 0.f;

    #pragma unroll
    for (int k = 0; k < 4; k++) {
        int pix = pslot*4 + k;
        int e0 = pix*36 + gbase;
        #pragma unroll
        for (int p = 0; p < 9; p++) {
            int e = e0 + p;
            int4   o  = toff[e];
            float4 wv = twt[e];
            corner_acc(xh + o.x, wv.x, res[k]);
            corner_acc(xh + o.y, wv.y, res[k]);
            corner_acc(xh + o.z, wv.z, res[k]);
            corner_acc(xh + o.w, wv.w, res[k]);
        }
    }

    // NCHW output: per channel, 4 consecutive w -> one float4 store
    #pragma unroll
    for (int u = 0; u < 8; u++) {
        int c = c8 + u;
        long base = ((long)(n*C_ + c)*H_ + h)*W_ + w0 + pslot*4;
        *reinterpret_cast<float4*>(out + base) =
            make_float4(res[0][u], res[1][u], res[2][u], res[3][u]);
    }
}

// ---------------- launch ----------------
extern "C" void kernel_launch(void* const* d_in, const int* in_sizes, int n_in,
                              void* d_out, int out_size) {
    const float* x    = (const float*)d_in[0];
    const float* unc  = (const float*)d_in[1];
    const float* dw_w = (const float*)d_in[2];
    const float* dw_b = (const float*)d_in[3];
    const float* gn_w = (const float*)d_in[4];
    const float* gn_b = (const float*)d_in[5];
    const float* om_w = (const float*)d_in[6];
    const float* om_b = (const float*)d_in[7];
    float* out = (float*)d_out;

    k0_init   <<<112, 256>>>(om_w);
    k1_dwconv <<<dim3(3, 8, N_*H_), dim3(32, 8)>>>(x, dw_w, dw_b);
    k3_gemm   <<<NPIX/64, 128>>>(gn_w, gn_b, om_b);
    k4_sample <<<NPIX/32, 256>>>(unc, out);
}